// round 2
// baseline (speedup 1.0000x reference)
#include <cuda_runtime.h>
#include <cstdint>

// ---------------------------------------------------------------------------
// EdgeScoringMLP: logit(e) = W3 . relu( relu(LN(e_in @ W1 + b1)) @ W2 + b2 ) + b3
//   e_in = [node_embed[i], node_embed[j], edge_attr]  (dim 258)
//
// Key decomposition: e_in @ W1 = Pa[i] + Pb[j] + a0*W1[256,:] + a1*W1[257,:]
//   Pa = node_embed @ W1[0:128,:]   (precomputed once per call)
//   Pb = node_embed @ W1[128:256,:]
//
// NOTE: edge_index_score is int32 (JAX x64 disabled demotes int64 -> int32).
// ---------------------------------------------------------------------------

#define HD 128
#define PCOL 256          // Pa (128) | Pb (128) per node, contiguous
#define MAXN 100000

__device__ float g_P[(size_t)MAXN * PCOL];

// ---------------------------------------------------------------------------
// Kernel 1: node projection precompute.
// P[n][o] = sum_c emb[n][c] * Wsel[c][o],
//   Wsel[c][o] = W1[c][o] (o<128)  /  W1[c+128][o-128] (o>=128)
// Block: 512 thr = 16 warps. Full Wsel (128x256 = 131 KB) staged in smem.
// Each warp computes 4 nodes; lane owns 8 output columns.
// ---------------------------------------------------------------------------
__global__ void __launch_bounds__(512, 1)
precompute_kernel(const float* __restrict__ emb,
                  const float* __restrict__ W1,
                  float* __restrict__ P,
                  int N)
{
    extern __shared__ float sm[];
    float* Ws = sm;               // [128][256]
    float* Xs = sm + 128 * 256;   // [16 warps][4 nodes][128]

    int tid = threadIdx.x;

    for (int t = tid; t < 128 * 256; t += 512) {
        int c = t >> 8, o = t & 255;
        float v = (o < 128) ? W1[c * HD + o] : W1[(c + 128) * HD + (o - 128)];
        Ws[t] = v;
    }
    __syncthreads();

    int w = tid >> 5, lane = tid & 31;
    float* xw = Xs + w * 4 * 128;

    long long grp = (long long)blockIdx.x * 16 + w;
    int n0 = (int)(grp * 4);
    if (n0 >= N) return;
    int nvalid = N - n0; if (nvalid > 4) nvalid = 4;

    #pragma unroll
    for (int nn = 0; nn < 4; nn++) {
        int n = n0 + ((nn < nvalid) ? nn : (nvalid - 1)); // clamp (dupes unused)
        float4 v = *(const float4*)(emb + (size_t)n * HD + 4 * lane);
        *(float4*)(xw + nn * 128 + 4 * lane) = v;
    }
    __syncwarp();

    float acc[4][8];
    #pragma unroll
    for (int nn = 0; nn < 4; nn++)
        #pragma unroll
        for (int j = 0; j < 8; j++) acc[nn][j] = 0.f;

    #pragma unroll 4
    for (int c = 0; c < 128; c++) {
        float4 w0 = *(const float4*)(Ws + c * 256 + lane * 8);
        float4 w1 = *(const float4*)(Ws + c * 256 + lane * 8 + 4);
        #pragma unroll
        for (int nn = 0; nn < 4; nn++) {
            float xv = xw[nn * 128 + c];   // warp broadcast
            acc[nn][0] += xv * w0.x; acc[nn][1] += xv * w0.y;
            acc[nn][2] += xv * w0.z; acc[nn][3] += xv * w0.w;
            acc[nn][4] += xv * w1.x; acc[nn][5] += xv * w1.y;
            acc[nn][6] += xv * w1.z; acc[nn][7] += xv * w1.w;
        }
    }

    for (int nn = 0; nn < nvalid; nn++) {
        float* dst = P + (size_t)(n0 + nn) * PCOL + lane * 8;
        *(float4*)dst       = make_float4(acc[nn][0], acc[nn][1], acc[nn][2], acc[nn][3]);
        *(float4*)(dst + 4) = make_float4(acc[nn][4], acc[nn][5], acc[nn][6], acc[nn][7]);
    }
}

// ---------------------------------------------------------------------------
// Kernel 2: fused edge pipeline.
// Block: 512 thr = 16 warps, each warp handles 4 edges.
// Per edge: gather Pa[i]+Pb[j], add attr terms + b1, warp-shuffle LayerNorm,
// ReLU -> x[128] in smem; register-tiled GEMM2 vs W2^T in smem, ReLU,
// dot with W3, warp-reduce.
// ---------------------------------------------------------------------------
__global__ void __launch_bounds__(512, 2)
edge_kernel(const float* __restrict__ P,
            const int* __restrict__ eidx,        // [2][E] int32
            const float* __restrict__ attr,      // [E][2]
            const float* __restrict__ W1,        // rows 256,257 used here
            const float* __restrict__ b1,
            const float* __restrict__ lng,
            const float* __restrict__ lnb,
            const float* __restrict__ W2,        // [128][64]
            const float* __restrict__ b2,        // [64]
            const float* __restrict__ W3,        // [64]
            const float* __restrict__ b3,        // [1]
            float* __restrict__ out,
            int E)
{
    extern __shared__ float sm[];
    float* W2T = sm;                    // [64][132] padded transpose
    float* Xs  = sm + 64 * 132;         // [16 warps][4 edges][128]
    float* w1a = Xs + 16 * 4 * 128;     // 128
    float* w1b = w1a + 128;             // 128
    float* b1s = w1b + 128;             // 128
    float* gs  = b1s + 128;             // 128
    float* bs  = gs + 128;              // 128
    float* w3s = bs + 128;              // 64
    float* b2s = w3s + 64;              // 64
    float* b3s = b2s + 64;              // 1

    int tid = threadIdx.x;

    for (int t = tid; t < 128 * 64; t += 512) {
        int c = t >> 6, o = t & 63;
        W2T[o * 132 + c] = W2[t];
    }
    if (tid < 128) {
        w1a[tid] = W1[256 * HD + tid];
        w1b[tid] = W1[257 * HD + tid];
        b1s[tid] = b1[tid];
        gs[tid]  = lng[tid];
        bs[tid]  = lnb[tid];
    }
    if (tid < 64) { w3s[tid] = W3[tid]; b2s[tid] = b2[tid]; }
    if (tid == 0) b3s[0] = b3[0];
    __syncthreads();

    int w = tid >> 5, lane = tid & 31;
    float* xw = Xs + w * 4 * 128;

    long long grp = (long long)blockIdx.x * 16 + w;
    long long e0  = grp * 4;
    if (e0 >= E) return;

    const float inv_h = 1.0f / 128.0f;

    // ---- gather + layernorm + relu for 4 edges ----
    #pragma unroll
    for (int nn = 0; nn < 4; nn++) {
        long long e = e0 + nn; if (e >= E) e = E - 1;
        int i = eidx[e];
        int j = eidx[(size_t)E + e];
        float a0 = attr[2 * e];
        float a1 = attr[2 * e + 1];

        float4 pa = *(const float4*)(P + (size_t)i * PCOL + 4 * lane);
        float4 pb = *(const float4*)(P + (size_t)j * PCOL + 128 + 4 * lane);
        int c0 = 4 * lane;
        float h0 = pa.x + pb.x + a0 * w1a[c0 + 0] + a1 * w1b[c0 + 0] + b1s[c0 + 0];
        float h1 = pa.y + pb.y + a0 * w1a[c0 + 1] + a1 * w1b[c0 + 1] + b1s[c0 + 1];
        float h2 = pa.z + pb.z + a0 * w1a[c0 + 2] + a1 * w1b[c0 + 2] + b1s[c0 + 2];
        float h3 = pa.w + pb.w + a0 * w1a[c0 + 3] + a1 * w1b[c0 + 3] + b1s[c0 + 3];

        float s  = h0 + h1 + h2 + h3;
        float sq = h0 * h0 + h1 * h1 + h2 * h2 + h3 * h3;
        #pragma unroll
        for (int off = 16; off > 0; off >>= 1) {
            s  += __shfl_xor_sync(0xffffffffu, s,  off);
            sq += __shfl_xor_sync(0xffffffffu, sq, off);
        }
        float mean = s * inv_h;
        float var  = sq * inv_h - mean * mean;
        float rstd = rsqrtf(var + 1e-5f);

        float4 xo;
        xo.x = fmaxf((h0 - mean) * rstd * gs[c0 + 0] + bs[c0 + 0], 0.f);
        xo.y = fmaxf((h1 - mean) * rstd * gs[c0 + 1] + bs[c0 + 1], 0.f);
        xo.z = fmaxf((h2 - mean) * rstd * gs[c0 + 2] + bs[c0 + 2], 0.f);
        xo.w = fmaxf((h3 - mean) * rstd * gs[c0 + 3] + bs[c0 + 3], 0.f);
        *(float4*)(xw + nn * 128 + c0) = xo;
    }
    __syncwarp();

    // ---- GEMM2: y[e][o] = x[e] . W2[:,o] + b2[o]; lane owns o=lane, lane+32 ----
    float acc0[4], acc1[4];
    #pragma unroll
    for (int nn = 0; nn < 4; nn++) { acc0[nn] = b2s[lane]; acc1[nn] = b2s[lane + 32]; }

    const float* w2r0 = W2T + (size_t)lane * 132;
    const float* w2r1 = W2T + (size_t)(lane + 32) * 132;
    #pragma unroll 4
    for (int c = 0; c < 128; c += 4) {
        float4 wv0 = *(const float4*)(w2r0 + c);
        float4 wv1 = *(const float4*)(w2r1 + c);
        #pragma unroll
        for (int nn = 0; nn < 4; nn++) {
            float4 xv = *(const float4*)(xw + nn * 128 + c);  // warp broadcast
            acc0[nn] += xv.x * wv0.x + xv.y * wv0.y + xv.z * wv0.z + xv.w * wv0.w;
            acc1[nn] += xv.x * wv1.x + xv.y * wv1.y + xv.z * wv1.z + xv.w * wv1.w;
        }
    }

    // ---- ReLU + W3 dot + warp reduction ----
    #pragma unroll
    for (int nn = 0; nn < 4; nn++) {
        float part = fmaxf(acc0[nn], 0.f) * w3s[lane]
                   + fmaxf(acc1[nn], 0.f) * w3s[lane + 32];
        #pragma unroll
        for (int off = 16; off > 0; off >>= 1)
            part += __shfl_xor_sync(0xffffffffu, part, off);
        if (lane == 0 && e0 + nn < E)
            out[e0 + nn] = part + b3s[0];
    }
}

// ---------------------------------------------------------------------------
// Launch
// ---------------------------------------------------------------------------
extern "C" void kernel_launch(void* const* d_in, const int* in_sizes, int n_in,
                              void* d_out, int out_size)
{
    const float* node_embed = (const float*)d_in[0];
    const int*   eidx       = (const int*)d_in[1];     // int32!
    const float* attr       = (const float*)d_in[2];
    const float* W1         = (const float*)d_in[3];
    const float* b1         = (const float*)d_in[4];
    const float* lng        = (const float*)d_in[5];
    const float* lnb        = (const float*)d_in[6];
    const float* W2         = (const float*)d_in[7];
    const float* b2         = (const float*)d_in[8];
    const float* W3         = (const float*)d_in[9];
    const float* b3         = (const float*)d_in[10];
    float* out = (float*)d_out;

    int N = in_sizes[0] / HD;
    int E = in_sizes[2] / 2;

    float* P = nullptr;
    cudaGetSymbolAddress((void**)&P, g_P);

    const int PRE_SMEM  = (128 * 256 + 16 * 4 * 128) * 4;               // 163840 B
    const int EDGE_SMEM = (64 * 132 + 16 * 4 * 128 + 5 * 128 + 64 + 64 + 1) * 4;

    cudaFuncSetAttribute(precompute_kernel,
                         cudaFuncAttributeMaxDynamicSharedMemorySize, PRE_SMEM);
    cudaFuncSetAttribute(edge_kernel,
                         cudaFuncAttributeMaxDynamicSharedMemorySize, EDGE_SMEM);

    int ngrp = (N + 3) / 4;
    int nblk = (ngrp + 15) / 16;
    precompute_kernel<<<nblk, 512, PRE_SMEM>>>(node_embed, W1, P, N);

    int egrp = (E + 3) / 4;
    int eblk = (egrp + 15) / 16;
    edge_kernel<<<eblk, 512, EDGE_SMEM>>>(P, eidx, attr, W1, b1, lng, lnb,
                                          W2, b2, W3, b3, out, E);
}

// round 3
// speedup vs baseline: 1.4704x; 1.4704x over previous
#include <cuda_runtime.h>
#include <cstdint>

// ---------------------------------------------------------------------------
// EdgeScoringMLP via tf32 tensor cores + Dekker hi/lo split (fp32 accuracy).
//   logit(e) = W3 . relu( relu(LN(e_in @ W1 + b1)) @ W2 + b2 ) + b3
//   e_in @ W1 = Pa[i] + Pb[j] + a0*W1[256,:] + a1*W1[257,:]   (P precomputed)
// edge_index_score buffer is int32 (JAX x64-disabled).
// ---------------------------------------------------------------------------

#define HD 128
#define PCOL 256
#define MAXN 100000

__device__ float g_P[(size_t)MAXN * PCOL];

// ---- tf32 helpers ---------------------------------------------------------
static __device__ __forceinline__ uint32_t f2tf32(float x) {
    uint32_t u;
    asm("cvt.rna.tf32.f32 %0, %1;" : "=r"(u) : "f"(x));
    return u;
}
static __device__ __forceinline__ void split_tf32(float x, uint32_t& hi, uint32_t& lo) {
    hi = f2tf32(x);
    float lof = x - __uint_as_float(hi);
    lo = f2tf32(lof);
}
static __device__ __forceinline__ void mma16n8k8(
    float& c0, float& c1, float& c2, float& c3,
    uint32_t a0, uint32_t a1, uint32_t a2, uint32_t a3,
    uint32_t b0, uint32_t b1)
{
    asm volatile(
        "mma.sync.aligned.m16n8k8.row.col.f32.tf32.tf32.f32 "
        "{%0,%1,%2,%3},{%4,%5,%6,%7},{%8,%9},{%0,%1,%2,%3};"
        : "+f"(c0), "+f"(c1), "+f"(c2), "+f"(c3)
        : "r"(a0), "r"(a1), "r"(a2), "r"(a3), "r"(b0), "r"(b1));
}

// ---------------------------------------------------------------------------
// Kernel 1: P = emb @ Wsel  (Wsel col o<128: W1[c][o]; o>=128: W1[c+128][o-128])
// CTA: 256 thr = 8 warps; tile = 64 nodes x 128 outputs (blockIdx.y = half).
// Warp (mt, nh): 16 nodes x 64 cols. 3-pass tf32 split.
// smem: As[64][132] fp32, Bs[128][136] fp32.
// ---------------------------------------------------------------------------
#define APAD 132
#define BPAD 136

__global__ void __launch_bounds__(256, 2)
precompute_kernel(const float* __restrict__ emb,
                  const float* __restrict__ W1,
                  float* __restrict__ P,
                  int N)
{
    extern __shared__ float sm[];
    float* As = sm;                 // [64][132]
    float* Bs = sm + 64 * APAD;     // [128][136]

    int tid  = threadIdx.x;
    int half = blockIdx.y;
    int n0g  = blockIdx.x * 64;     // first node of tile

    // stage A (64 nodes x 128), clamp rows
    for (int t = tid; t < 64 * 32; t += 256) {
        int r = t >> 5, cq = (t & 31) * 4;
        int node = n0g + r; if (node >= N) node = N - 1;
        float4 v = *(const float4*)(emb + (size_t)node * HD + cq);
        *(float4*)(As + r * APAD + cq) = v;
    }
    // stage B half (128 x 128) : Bs[c][o] = W1[(c + half*128)][o]
    for (int t = tid; t < 128 * 128; t += 256) {
        int c = t >> 7, o = t & 127;
        Bs[c * BPAD + o] = W1[(size_t)(c + half * 128) * HD + o];
    }
    __syncthreads();

    int wid = tid >> 5, lane = tid & 31;
    int g = lane >> 2, tig = lane & 3;
    int mt = wid >> 1, nh = wid & 1;
    int m0 = mt * 16;           // local row base
    int c0w = nh * 64;          // local col base within half

    float C[8][4];
    #pragma unroll
    for (int nt = 0; nt < 8; nt++)
        #pragma unroll
        for (int q = 0; q < 4; q++) C[nt][q] = 0.f;

    #pragma unroll
    for (int k = 0; k < 16; k++) {
        int kr = 8 * k + tig;
        uint32_t ahi[4], alo[4];
        split_tf32(As[(m0 + g)     * APAD + kr],     ahi[0], alo[0]);
        split_tf32(As[(m0 + g + 8) * APAD + kr],     ahi[1], alo[1]);
        split_tf32(As[(m0 + g)     * APAD + kr + 4], ahi[2], alo[2]);
        split_tf32(As[(m0 + g + 8) * APAD + kr + 4], ahi[3], alo[3]);
        #pragma unroll
        for (int nt = 0; nt < 8; nt++) {
            int nc = c0w + 8 * nt + g;
            uint32_t bh0, bl0, bh1, bl1;
            split_tf32(Bs[kr       * BPAD + nc], bh0, bl0);
            split_tf32(Bs[(kr + 4) * BPAD + nc], bh1, bl1);
            mma16n8k8(C[nt][0], C[nt][1], C[nt][2], C[nt][3],
                      ahi[0], ahi[1], ahi[2], ahi[3], bh0, bh1);
            mma16n8k8(C[nt][0], C[nt][1], C[nt][2], C[nt][3],
                      ahi[0], ahi[1], ahi[2], ahi[3], bl0, bl1);
            mma16n8k8(C[nt][0], C[nt][1], C[nt][2], C[nt][3],
                      alo[0], alo[1], alo[2], alo[3], bh0, bh1);
        }
    }

    // write P: rows n0g+m0+g (+8), cols half*128 + c0w + 8nt + 2tig (+1)
    int r0 = n0g + m0 + g;
    int r1 = r0 + 8;
    #pragma unroll
    for (int nt = 0; nt < 8; nt++) {
        int col = half * 128 + c0w + 8 * nt + 2 * tig;
        if (r0 < N) *(float2*)(P + (size_t)r0 * PCOL + col) = make_float2(C[nt][0], C[nt][1]);
        if (r1 < N) *(float2*)(P + (size_t)r1 * PCOL + col) = make_float2(C[nt][2], C[nt][3]);
    }
}

// ---------------------------------------------------------------------------
// Kernel 2: persistent fused edge pipeline.
// 256 thr = 8 warps; each warp owns chunks of 16 edges (strided).
// Per chunk: gather Pa[i]+Pb[j]+attr terms+b1 -> LN -> ReLU -> X[16][132] smem
// (warp-private, no block sync), then tf32 3-pass mma vs W2 (smem [128][72]),
// bias-in-accumulator, ReLU, W3 dot in C-registers, shuffle reduce.
// ---------------------------------------------------------------------------
#define W2PAD 72
#define XPAD 132

__global__ void __launch_bounds__(256, 2)
edge_kernel(const float* __restrict__ P,
            const int* __restrict__ eidx,        // [2][E] int32
            const float* __restrict__ attr,      // [E][2]
            const float* __restrict__ W1,        // rows 256,257
            const float* __restrict__ b1,
            const float* __restrict__ lng,
            const float* __restrict__ lnb,
            const float* __restrict__ W2,        // [128][64]
            const float* __restrict__ b2,
            const float* __restrict__ W3,
            const float* __restrict__ b3,
            float* __restrict__ out,
            int E)
{
    extern __shared__ float sm[];
    float* W2s = sm;                        // [128][72]
    float* Xs  = W2s + 128 * W2PAD;         // [8 warps][16][132]
    float* w1a = Xs + 8 * 16 * XPAD;        // 128
    float* w1b = w1a + 128;
    float* b1s = w1b + 128;
    float* gs  = b1s + 128;
    float* bs  = gs + 128;
    float* w3s = bs + 128;                  // 64
    float* b2s = w3s + 64;                  // 64
    float* b3s = b2s + 64;                  // 1

    int tid = threadIdx.x;

    for (int t = tid; t < 128 * 64; t += 256) {
        int c = t >> 6, o = t & 63;
        W2s[c * W2PAD + o] = W2[t];
    }
    if (tid < 128) {
        w1a[tid] = W1[256 * HD + tid];
        w1b[tid] = W1[257 * HD + tid];
        b1s[tid] = b1[tid];
        gs[tid]  = lng[tid];
        bs[tid]  = lnb[tid];
    }
    if (tid < 64) { w3s[tid] = W3[tid]; b2s[tid] = b2[tid]; }
    if (tid == 0) b3s[0] = b3[0];
    __syncthreads();

    int wid = tid >> 5, lane = tid & 31;
    int g = lane >> 2, tig = lane & 3;
    float* Xw = Xs + wid * 16 * XPAD;
    int c0 = 4 * lane;
    const float inv_h = 1.0f / 128.0f;
    float b3v = b3s[0];

    int nchunks = (E + 15) >> 4;
    int wg = blockIdx.x * 8 + wid;
    int wstride = gridDim.x * 8;

    for (int ch = wg; ch < nchunks; ch += wstride) {
        int e_base = ch << 4;

        // ---- gather + LN + ReLU -> Xw[16][132] ----
        #pragma unroll 4
        for (int ee = 0; ee < 16; ee++) {
            int e = e_base + ee; if (e >= E) e = E - 1;
            int i = eidx[e];
            int j = eidx[(size_t)E + e];
            float a0 = attr[2 * e];
            float a1 = attr[2 * e + 1];

            float4 pa = *(const float4*)(P + (size_t)i * PCOL + c0);
            float4 pb = *(const float4*)(P + (size_t)j * PCOL + 128 + c0);

            float h0 = pa.x + pb.x + a0 * w1a[c0 + 0] + a1 * w1b[c0 + 0] + b1s[c0 + 0];
            float h1 = pa.y + pb.y + a0 * w1a[c0 + 1] + a1 * w1b[c0 + 1] + b1s[c0 + 1];
            float h2 = pa.z + pb.z + a0 * w1a[c0 + 2] + a1 * w1b[c0 + 2] + b1s[c0 + 2];
            float h3 = pa.w + pb.w + a0 * w1a[c0 + 3] + a1 * w1b[c0 + 3] + b1s[c0 + 3];

            float s  = h0 + h1 + h2 + h3;
            float sq = h0 * h0 + h1 * h1 + h2 * h2 + h3 * h3;
            #pragma unroll
            for (int off = 16; off > 0; off >>= 1) {
                s  += __shfl_xor_sync(0xffffffffu, s,  off);
                sq += __shfl_xor_sync(0xffffffffu, sq, off);
            }
            float mean = s * inv_h;
            float var  = sq * inv_h - mean * mean;
            float rstd = rsqrtf(var + 1e-5f);

            float4 xo;
            xo.x = fmaxf((h0 - mean) * rstd * gs[c0 + 0] + bs[c0 + 0], 0.f);
            xo.y = fmaxf((h1 - mean) * rstd * gs[c0 + 1] + bs[c0 + 1], 0.f);
            xo.z = fmaxf((h2 - mean) * rstd * gs[c0 + 2] + bs[c0 + 2], 0.f);
            xo.w = fmaxf((h3 - mean) * rstd * gs[c0 + 3] + bs[c0 + 3], 0.f);
            *(float4*)(Xw + ee * XPAD + c0) = xo;
        }
        __syncwarp();

        // ---- GEMM2 on tensor cores: C[16][64] = X @ W2 + b2 ----
        float C[8][4];
        #pragma unroll
        for (int nt = 0; nt < 8; nt++) {
            float bb0 = b2s[8 * nt + 2 * tig];
            float bb1 = b2s[8 * nt + 2 * tig + 1];
            C[nt][0] = bb0; C[nt][1] = bb1;
            C[nt][2] = bb0; C[nt][3] = bb1;
        }

        #pragma unroll
        for (int k = 0; k < 16; k++) {
            int kr = 8 * k + tig;
            uint32_t ahi[4], alo[4];
            split_tf32(Xw[g       * XPAD + kr],     ahi[0], alo[0]);
            split_tf32(Xw[(g + 8) * XPAD + kr],     ahi[1], alo[1]);
            split_tf32(Xw[g       * XPAD + kr + 4], ahi[2], alo[2]);
            split_tf32(Xw[(g + 8) * XPAD + kr + 4], ahi[3], alo[3]);
            #pragma unroll
            for (int nt = 0; nt < 8; nt++) {
                int nc = 8 * nt + g;
                uint32_t bh0, bl0, bh1, bl1;
                split_tf32(W2s[kr       * W2PAD + nc], bh0, bl0);
                split_tf32(W2s[(kr + 4) * W2PAD + nc], bh1, bl1);
                mma16n8k8(C[nt][0], C[nt][1], C[nt][2], C[nt][3],
                          ahi[0], ahi[1], ahi[2], ahi[3], bh0, bh1);
                mma16n8k8(C[nt][0], C[nt][1], C[nt][2], C[nt][3],
                          ahi[0], ahi[1], ahi[2], ahi[3], bl0, bl1);
                mma16n8k8(C[nt][0], C[nt][1], C[nt][2], C[nt][3],
                          alo[0], alo[1], alo[2], alo[3], bh0, bh1);
            }
        }

        // ---- ReLU + W3 dot (in C regs) + reduce over tig ----
        float p0 = 0.f, p1 = 0.f;
        #pragma unroll
        for (int nt = 0; nt < 8; nt++) {
            float w30 = w3s[8 * nt + 2 * tig];
            float w31 = w3s[8 * nt + 2 * tig + 1];
            p0 += fmaxf(C[nt][0], 0.f) * w30 + fmaxf(C[nt][1], 0.f) * w31;
            p1 += fmaxf(C[nt][2], 0.f) * w30 + fmaxf(C[nt][3], 0.f) * w31;
        }
        p0 += __shfl_xor_sync(0xffffffffu, p0, 1);
        p0 += __shfl_xor_sync(0xffffffffu, p0, 2);
        p1 += __shfl_xor_sync(0xffffffffu, p1, 1);
        p1 += __shfl_xor_sync(0xffffffffu, p1, 2);

        if (tig == 0) {
            int er0 = e_base + g;
            int er1 = e_base + g + 8;
            if (er0 < E) out[er0] = p0 + b3v;
            if (er1 < E) out[er1] = p1 + b3v;
        }
    }
}

// ---------------------------------------------------------------------------
// Launch
// ---------------------------------------------------------------------------
extern "C" void kernel_launch(void* const* d_in, const int* in_sizes, int n_in,
                              void* d_out, int out_size)
{
    const float* node_embed = (const float*)d_in[0];
    const int*   eidx       = (const int*)d_in[1];
    const float* attr       = (const float*)d_in[2];
    const float* W1         = (const float*)d_in[3];
    const float* b1         = (const float*)d_in[4];
    const float* lng        = (const float*)d_in[5];
    const float* lnb        = (const float*)d_in[6];
    const float* W2         = (const float*)d_in[7];
    const float* b2         = (const float*)d_in[8];
    const float* W3         = (const float*)d_in[9];
    const float* b3         = (const float*)d_in[10];
    float* out = (float*)d_out;

    int N = in_sizes[0] / HD;
    int E = in_sizes[2] / 2;

    float* P = nullptr;
    cudaGetSymbolAddress((void**)&P, g_P);

    const int PRE_SMEM  = (64 * APAD + 128 * BPAD) * 4;                 // 103424 B
    const int EDGE_SMEM = (128 * W2PAD + 8 * 16 * XPAD + 5 * 128 + 64 + 64 + 1) * 4;

    cudaFuncSetAttribute(precompute_kernel,
                         cudaFuncAttributeMaxDynamicSharedMemorySize, PRE_SMEM);
    cudaFuncSetAttribute(edge_kernel,
                         cudaFuncAttributeMaxDynamicSharedMemorySize, EDGE_SMEM);

    dim3 pre_grid((N + 63) / 64, 2);
    precompute_kernel<<<pre_grid, 256, PRE_SMEM>>>(node_embed, W1, P, N);

    edge_kernel<<<296, 256, EDGE_SMEM>>>(P, eidx, attr, W1, b1, lng, lnb,
                                         W2, b2, W3, b3, out, E);
}

// round 4
// speedup vs baseline: 2.1588x; 1.4681x over previous
#include <cuda_runtime.h>
#include <cstdint>

// ---------------------------------------------------------------------------
// EdgeScoringMLP via bf16 tensor cores + 3-pass Dekker split (hi*hi+hi*lo+lo*hi).
//   logit(e) = W3 . relu( relu(LN(e_in @ W1 + b1)) @ W2 + b2 ) + b3
//   e_in @ W1 = Pa[i] + Pb[j] + a0*W1[256,:] + a1*W1[257,:]   (P precomputed)
// Weights pre-split into packed bf16x2 hi/lo smem arrays once per CTA.
// edge_index_score buffer is int32 (JAX x64-disabled).
// ---------------------------------------------------------------------------

#define HD 128
#define PCOL 256
#define MAXN 100000
#define PW 68              // padded row stride (u32 units): (4g+tig)%32 all-distinct

__device__ float g_P[(size_t)MAXN * PCOL];

// ---- bf16 helpers ---------------------------------------------------------
static __device__ __forceinline__ uint32_t pack_bf16x2(float lo, float hi) {
    // result = {upper = cvt(hi), lower = cvt(lo)}
    uint32_t d;
    asm("cvt.rn.bf16x2.f32 %0, %1, %2;" : "=r"(d) : "f"(hi), "f"(lo));
    return d;
}
// split pair (x0 -> low lane, x1 -> high lane) into hi/lo bf16x2 words
static __device__ __forceinline__ void split_pair(float x0, float x1,
                                                  uint32_t& hi, uint32_t& lo) {
    hi = pack_bf16x2(x0, x1);
    float h0 = __uint_as_float(hi << 16);
    float h1 = __uint_as_float(hi & 0xFFFF0000u);
    lo = pack_bf16x2(x0 - h0, x1 - h1);
}
static __device__ __forceinline__ void mma_bf16(
    float& c0, float& c1, float& c2, float& c3,
    uint32_t a0, uint32_t a1, uint32_t a2, uint32_t a3,
    uint32_t b0, uint32_t b1)
{
    asm volatile(
        "mma.sync.aligned.m16n8k16.row.col.f32.bf16.bf16.f32 "
        "{%0,%1,%2,%3},{%4,%5,%6,%7},{%8,%9},{%0,%1,%2,%3};"
        : "+f"(c0), "+f"(c1), "+f"(c2), "+f"(c3)
        : "r"(a0), "r"(a1), "r"(a2), "r"(a3), "r"(b0), "r"(b1));
}

// ---------------------------------------------------------------------------
// Kernel 1: P = emb @ Wsel.  Wsel col o (within half): W1[c + half*128][o].
// CTA 256 thr = 8 warps; tile 64 nodes x 128 cols (blockIdx.y = half).
// Warp (mt, nh): 16 nodes x 64 cols. smem: packed bf16x2 hi/lo for A and W.
// ---------------------------------------------------------------------------
__global__ void __launch_bounds__(256, 2)
precompute_kernel(const float* __restrict__ emb,
                  const float* __restrict__ W1,
                  float* __restrict__ P,
                  int N)
{
    extern __shared__ uint32_t smu[];
    uint32_t* Whi = smu;                  // [128][PW]
    uint32_t* Wlo = Whi + 128 * PW;
    uint32_t* Ahi = Wlo + 128 * PW;       // [64][PW]
    uint32_t* Alo = Ahi + 64 * PW;

    int tid  = threadIdx.x;
    int half = blockIdx.y;
    int n0g  = blockIdx.x * 64;

    // stage + split W half: Whi/Wlo[o][kp] = split(W1[2kp+half*128][o], W1[2kp+1+...][o])
    for (int t = tid; t < 128 * 64; t += 256) {
        int kp = t >> 7, o = t & 127;
        float e0 = W1[(size_t)(2 * kp     + half * 128) * HD + o];
        float e1 = W1[(size_t)(2 * kp + 1 + half * 128) * HD + o];
        uint32_t hi, lo; split_pair(e0, e1, hi, lo);
        Whi[o * PW + kp] = hi; Wlo[o * PW + kp] = lo;
    }
    // stage + split A tile: Ahi/Alo[r][kp] from emb[n0g+r][2kp..2kp+1]
    for (int t = tid; t < 64 * 64; t += 256) {
        int r = t >> 6, kp = t & 63;
        int node = n0g + r; if (node >= N) node = N - 1;
        float2 v = *(const float2*)(emb + (size_t)node * HD + 2 * kp);
        uint32_t hi, lo; split_pair(v.x, v.y, hi, lo);
        Ahi[r * PW + kp] = hi; Alo[r * PW + kp] = lo;
    }
    __syncthreads();

    int wid = tid >> 5, lane = tid & 31;
    int g = lane >> 2, tig = lane & 3;
    int mt = wid >> 1, nh = wid & 1;
    int m0 = mt * 16;

    float C[8][4];
    #pragma unroll
    for (int nt = 0; nt < 8; nt++)
        #pragma unroll
        for (int q = 0; q < 4; q++) C[nt][q] = 0.f;

    #pragma unroll
    for (int kt = 0; kt < 8; kt++) {
        int kb = kt * 8 + tig;
        uint32_t ah0 = Ahi[(m0 + g)     * PW + kb];
        uint32_t ah1 = Ahi[(m0 + g + 8) * PW + kb];
        uint32_t ah2 = Ahi[(m0 + g)     * PW + kb + 4];
        uint32_t ah3 = Ahi[(m0 + g + 8) * PW + kb + 4];
        uint32_t al0 = Alo[(m0 + g)     * PW + kb];
        uint32_t al1 = Alo[(m0 + g + 8) * PW + kb];
        uint32_t al2 = Alo[(m0 + g)     * PW + kb + 4];
        uint32_t al3 = Alo[(m0 + g + 8) * PW + kb + 4];
        #pragma unroll
        for (int nt = 0; nt < 8; nt++) {
            int nc = nh * 64 + nt * 8 + g;
            uint32_t bh0 = Whi[nc * PW + kb], bh1 = Whi[nc * PW + kb + 4];
            uint32_t bl0 = Wlo[nc * PW + kb], bl1 = Wlo[nc * PW + kb + 4];
            mma_bf16(C[nt][0], C[nt][1], C[nt][2], C[nt][3],
                     ah0, ah1, ah2, ah3, bh0, bh1);
            mma_bf16(C[nt][0], C[nt][1], C[nt][2], C[nt][3],
                     ah0, ah1, ah2, ah3, bl0, bl1);
            mma_bf16(C[nt][0], C[nt][1], C[nt][2], C[nt][3],
                     al0, al1, al2, al3, bh0, bh1);
        }
    }

    int r0 = n0g + m0 + g;
    int r1 = r0 + 8;
    #pragma unroll
    for (int nt = 0; nt < 8; nt++) {
        int col = half * 128 + nh * 64 + nt * 8 + 2 * tig;
        if (r0 < N) *(float2*)(P + (size_t)r0 * PCOL + col) = make_float2(C[nt][0], C[nt][1]);
        if (r1 < N) *(float2*)(P + (size_t)r1 * PCOL + col) = make_float2(C[nt][2], C[nt][3]);
    }
}

// ---------------------------------------------------------------------------
// Kernel 2: persistent fused edge pipeline (bf16 mma).
// 256 thr = 8 warps; each warp owns chunks of 16 edges (grid-strided).
// gather Pa[i]+Pb[j]+attr+b1 -> LN -> ReLU -> split-pack into Xhi/Xlo smem,
// then 3-pass bf16 mma vs pre-split W2, bias-in-C, ReLU, W3 dot, reduce.
// ---------------------------------------------------------------------------
__global__ void __launch_bounds__(256, 2)
edge_kernel(const float* __restrict__ P,
            const int* __restrict__ eidx,        // [2][E] int32
            const float* __restrict__ attr,      // [E][2]
            const float* __restrict__ W1,        // rows 256,257
            const float* __restrict__ b1,
            const float* __restrict__ lng,
            const float* __restrict__ lnb,
            const float* __restrict__ W2,        // [128][64]
            const float* __restrict__ b2,
            const float* __restrict__ W3,
            const float* __restrict__ b3,
            float* __restrict__ out,
            int E)
{
    extern __shared__ uint32_t smu[];
    uint32_t* W2hi = smu;                     // [64][PW]
    uint32_t* W2lo = W2hi + 64 * PW;
    uint32_t* Xbase = W2lo + 64 * PW;         // 8 warps x (Xhi[16][PW] + Xlo[16][PW])
    float* cf  = (float*)(Xbase + 8 * 2 * 16 * PW);
    float* w1a = cf;            // 128
    float* w1b = w1a + 128;
    float* b1s = w1b + 128;
    float* gs  = b1s + 128;
    float* bs  = gs + 128;
    float* w3s = bs + 128;      // 64
    float* b2s = w3s + 64;      // 64
    float* b3s = b2s + 64;      // 1

    int tid = threadIdx.x;

    // pre-split W2 -> packed bf16x2 hi/lo: W2hi[o][kp] = split(W2[2kp][o], W2[2kp+1][o])
    for (int t = tid; t < 64 * 64; t += 256) {
        int kp = t >> 6, o = t & 63;
        float e0 = W2[(size_t)(2 * kp)     * 64 + o];
        float e1 = W2[(size_t)(2 * kp + 1) * 64 + o];
        uint32_t hi, lo; split_pair(e0, e1, hi, lo);
        W2hi[o * PW + kp] = hi; W2lo[o * PW + kp] = lo;
    }
    if (tid < 128) {
        w1a[tid] = W1[256 * HD + tid];
        w1b[tid] = W1[257 * HD + tid];
        b1s[tid] = b1[tid];
        gs[tid]  = lng[tid];
        bs[tid]  = lnb[tid];
    }
    if (tid < 64) { w3s[tid] = W3[tid]; b2s[tid] = b2[tid]; }
    if (tid == 0) b3s[0] = b3[0];
    __syncthreads();

    int wid = tid >> 5, lane = tid & 31;
    int g = lane >> 2, tig = lane & 3;
    uint32_t* Xhi = Xbase + wid * 2 * 16 * PW;
    uint32_t* Xlo = Xhi + 16 * PW;
    int c0 = 4 * lane;
    const float inv_h = 1.0f / 128.0f;
    float b3v = b3s[0];
    const float2* attr2 = (const float2*)attr;

    int nchunks = (E + 15) >> 4;
    int wg = blockIdx.x * 8 + wid;
    int wstride = gridDim.x * 8;

    for (int ch = wg; ch < nchunks; ch += wstride) {
        int e_base = ch << 4;

        // ---- gather + LN + ReLU + split-pack -> Xhi/Xlo ----
        #pragma unroll 4
        for (int ee = 0; ee < 16; ee++) {
            int e = e_base + ee; if (e >= E) e = E - 1;
            int i = eidx[e];
            int j = eidx[(size_t)E + e];
            float2 a = attr2[e];

            float4 pa = *(const float4*)(P + (size_t)i * PCOL + c0);
            float4 pb = *(const float4*)(P + (size_t)j * PCOL + 128 + c0);

            float h0 = pa.x + pb.x + a.x * w1a[c0 + 0] + a.y * w1b[c0 + 0] + b1s[c0 + 0];
            float h1 = pa.y + pb.y + a.x * w1a[c0 + 1] + a.y * w1b[c0 + 1] + b1s[c0 + 1];
            float h2 = pa.z + pb.z + a.x * w1a[c0 + 2] + a.y * w1b[c0 + 2] + b1s[c0 + 2];
            float h3 = pa.w + pb.w + a.x * w1a[c0 + 3] + a.y * w1b[c0 + 3] + b1s[c0 + 3];

            float s  = h0 + h1 + h2 + h3;
            float sq = h0 * h0 + h1 * h1 + h2 * h2 + h3 * h3;
            #pragma unroll
            for (int off = 16; off > 0; off >>= 1) {
                s  += __shfl_xor_sync(0xffffffffu, s,  off);
                sq += __shfl_xor_sync(0xffffffffu, sq, off);
            }
            float mean = s * inv_h;
            float var  = sq * inv_h - mean * mean;
            float rstd = rsqrtf(var + 1e-5f);

            float x0 = fmaxf((h0 - mean) * rstd * gs[c0 + 0] + bs[c0 + 0], 0.f);
            float x1 = fmaxf((h1 - mean) * rstd * gs[c0 + 1] + bs[c0 + 1], 0.f);
            float x2 = fmaxf((h2 - mean) * rstd * gs[c0 + 2] + bs[c0 + 2], 0.f);
            float x3 = fmaxf((h3 - mean) * rstd * gs[c0 + 3] + bs[c0 + 3], 0.f);

            uint32_t hA, lA, hB, lB;
            split_pair(x0, x1, hA, lA);
            split_pair(x2, x3, hB, lB);
            *(uint2*)(Xhi + ee * PW + 2 * lane) = make_uint2(hA, hB);
            *(uint2*)(Xlo + ee * PW + 2 * lane) = make_uint2(lA, lB);
        }
        __syncwarp();

        // ---- GEMM2: C[16][64] = X @ W2 + b2, 3-pass bf16 ----
        float C[8][4];
        #pragma unroll
        for (int nt = 0; nt < 8; nt++) {
            float bb0 = b2s[8 * nt + 2 * tig];
            float bb1 = b2s[8 * nt + 2 * tig + 1];
            C[nt][0] = bb0; C[nt][1] = bb1;
            C[nt][2] = bb0; C[nt][3] = bb1;
        }

        #pragma unroll
        for (int kt = 0; kt < 8; kt++) {
            int kb = kt * 8 + tig;
            uint32_t ah0 = Xhi[g       * PW + kb];
            uint32_t ah1 = Xhi[(g + 8) * PW + kb];
            uint32_t ah2 = Xhi[g       * PW + kb + 4];
            uint32_t ah3 = Xhi[(g + 8) * PW + kb + 4];
            uint32_t al0 = Xlo[g       * PW + kb];
            uint32_t al1 = Xlo[(g + 8) * PW + kb];
            uint32_t al2 = Xlo[g       * PW + kb + 4];
            uint32_t al3 = Xlo[(g + 8) * PW + kb + 4];
            #pragma unroll
            for (int nt = 0; nt < 8; nt++) {
                int nc = 8 * nt + g;
                uint32_t bh0 = W2hi[nc * PW + kb], bh1 = W2hi[nc * PW + kb + 4];
                uint32_t bl0 = W2lo[nc * PW + kb], bl1 = W2lo[nc * PW + kb + 4];
                mma_bf16(C[nt][0], C[nt][1], C[nt][2], C[nt][3],
                         ah0, ah1, ah2, ah3, bh0, bh1);
                mma_bf16(C[nt][0], C[nt][1], C[nt][2], C[nt][3],
                         ah0, ah1, ah2, ah3, bl0, bl1);
                mma_bf16(C[nt][0], C[nt][1], C[nt][2], C[nt][3],
                         al0, al1, al2, al3, bh0, bh1);
            }
        }
        __syncwarp();

        // ---- ReLU + W3 dot + reduce over tig ----
        float p0 = 0.f, p1 = 0.f;
        #pragma unroll
        for (int nt = 0; nt < 8; nt++) {
            float w30 = w3s[8 * nt + 2 * tig];
            float w31 = w3s[8 * nt + 2 * tig + 1];
            p0 += fmaxf(C[nt][0], 0.f) * w30 + fmaxf(C[nt][1], 0.f) * w31;
            p1 += fmaxf(C[nt][2], 0.f) * w30 + fmaxf(C[nt][3], 0.f) * w31;
        }
        p0 += __shfl_xor_sync(0xffffffffu, p0, 1);
        p0 += __shfl_xor_sync(0xffffffffu, p0, 2);
        p1 += __shfl_xor_sync(0xffffffffu, p1, 1);
        p1 += __shfl_xor_sync(0xffffffffu, p1, 2);

        if (tig == 0) {
            int er0 = e_base + g;
            int er1 = e_base + g + 8;
            if (er0 < E) out[er0] = p0 + b3v;
            if (er1 < E) out[er1] = p1 + b3v;
        }
    }
}

// ---------------------------------------------------------------------------
// Launch
// ---------------------------------------------------------------------------
extern "C" void kernel_launch(void* const* d_in, const int* in_sizes, int n_in,
                              void* d_out, int out_size)
{
    const float* node_embed = (const float*)d_in[0];
    const int*   eidx       = (const int*)d_in[1];
    const float* attr       = (const float*)d_in[2];
    const float* W1         = (const float*)d_in[3];
    const float* b1         = (const float*)d_in[4];
    const float* lng        = (const float*)d_in[5];
    const float* lnb        = (const float*)d_in[6];
    const float* W2         = (const float*)d_in[7];
    const float* b2         = (const float*)d_in[8];
    const float* W3         = (const float*)d_in[9];
    const float* b3         = (const float*)d_in[10];
    float* out = (float*)d_out;

    int N = in_sizes[0] / HD;
    int E = in_sizes[2] / 2;

    float* P = nullptr;
    cudaGetSymbolAddress((void**)&P, g_P);

    const int PRE_SMEM  = (2 * 128 * PW + 2 * 64 * PW) * 4;                    // 104448 B
    const int EDGE_SMEM = (2 * 64 * PW + 8 * 2 * 16 * PW + 769) * 4;           // 107524 B

    cudaFuncSetAttribute(precompute_kernel,
                         cudaFuncAttributeMaxDynamicSharedMemorySize, PRE_SMEM);
    cudaFuncSetAttribute(edge_kernel,
                         cudaFuncAttributeMaxDynamicSharedMemorySize, EDGE_SMEM);

    dim3 pre_grid((N + 63) / 64, 2);
    precompute_kernel<<<pre_grid, 256, PRE_SMEM>>>(node_embed, W1, P, N);

    edge_kernel<<<296, 256, EDGE_SMEM>>>(P, eidx, attr, W1, b1, lng, lnb,
                                         W2, b2, W3, b3, out, E);
}

// round 5
// speedup vs baseline: 2.1864x; 1.0128x over previous
#include <cuda_runtime.h>
#include <cstdint>

// ---------------------------------------------------------------------------
// EdgeScoringMLP via bf16 tensor cores + 3-pass Dekker split (hi*hi+hi*lo+lo*hi).
//   logit(e) = W3 . relu( relu(LN(e_in @ W1 + b1)) @ W2 + b2 ) + b3
//   e_in @ W1 = Pa[i] + Pb[j] + a0*W1[256,:] + a1*W1[257,:]   (P precomputed)
// R5: LN consts hoisted to regs, lane-parallel edge-index prefetch,
//     M=32 per warp (2 mma row-tiles share B fragments), same for precompute.
// ---------------------------------------------------------------------------

#define HD 128
#define PCOL 256
#define MAXN 100000
#define PW 68              // padded row stride (u32): (4g+tig)%32 all-distinct

__device__ float g_P[(size_t)MAXN * PCOL];

// ---- bf16 helpers ---------------------------------------------------------
static __device__ __forceinline__ uint32_t pack_bf16x2(float lo, float hi) {
    uint32_t d;
    asm("cvt.rn.bf16x2.f32 %0, %1, %2;" : "=r"(d) : "f"(hi), "f"(lo));
    return d;
}
static __device__ __forceinline__ void split_pair(float x0, float x1,
                                                  uint32_t& hi, uint32_t& lo) {
    hi = pack_bf16x2(x0, x1);
    float h0 = __uint_as_float(hi << 16);
    float h1 = __uint_as_float(hi & 0xFFFF0000u);
    lo = pack_bf16x2(x0 - h0, x1 - h1);
}
static __device__ __forceinline__ void mma_bf16(
    float& c0, float& c1, float& c2, float& c3,
    uint32_t a0, uint32_t a1, uint32_t a2, uint32_t a3,
    uint32_t b0, uint32_t b1)
{
    asm volatile(
        "mma.sync.aligned.m16n8k16.row.col.f32.bf16.bf16.f32 "
        "{%0,%1,%2,%3},{%4,%5,%6,%7},{%8,%9},{%0,%1,%2,%3};"
        : "+f"(c0), "+f"(c1), "+f"(c2), "+f"(c3)
        : "r"(a0), "r"(a1), "r"(a2), "r"(a3), "r"(b0), "r"(b1));
}

// ---------------------------------------------------------------------------
// Kernel 1: P = emb @ Wsel. CTA 256 thr = 8 warps, tile 128 nodes x 128 cols
// (blockIdx.y = half). Warp (mt 0..3, nh 0..1): 32 nodes x 64 cols, two
// 16-row mma tiles sharing B fragments.
// ---------------------------------------------------------------------------
__global__ void __launch_bounds__(256, 1)
precompute_kernel(const float* __restrict__ emb,
                  const float* __restrict__ W1,
                  float* __restrict__ P,
                  int N)
{
    extern __shared__ uint32_t smu[];
    uint32_t* Whi = smu;                  // [128][PW]  (o-major)
    uint32_t* Wlo = Whi + 128 * PW;
    uint32_t* Ahi = Wlo + 128 * PW;       // [128][PW]  (node-row major)
    uint32_t* Alo = Ahi + 128 * PW;

    int tid  = threadIdx.x;
    int half = blockIdx.y;
    int n0g  = blockIdx.x * 128;

    for (int t = tid; t < 128 * 64; t += 256) {
        int o = t & 127, kp = t >> 7;
        float e0 = W1[(size_t)(2 * kp     + half * 128) * HD + o];
        float e1 = W1[(size_t)(2 * kp + 1 + half * 128) * HD + o];
        uint32_t hi, lo; split_pair(e0, e1, hi, lo);
        Whi[o * PW + kp] = hi; Wlo[o * PW + kp] = lo;
    }
    for (int t = tid; t < 128 * 64; t += 256) {
        int r = t >> 6, kp = t & 63;
        int node = n0g + r; if (node >= N) node = N - 1;
        float2 v = *(const float2*)(emb + (size_t)node * HD + 2 * kp);
        uint32_t hi, lo; split_pair(v.x, v.y, hi, lo);
        Ahi[r * PW + kp] = hi; Alo[r * PW + kp] = lo;
    }
    __syncthreads();

    int wid = tid >> 5, lane = tid & 31;
    int g = lane >> 2, tig = lane & 3;
    int mt = wid >> 1, nh = wid & 1;
    int m0 = mt * 32;

    float C[2][8][4];
    #pragma unroll
    for (int tt = 0; tt < 2; tt++)
        #pragma unroll
        for (int nt = 0; nt < 8; nt++)
            #pragma unroll
            for (int q = 0; q < 4; q++) C[tt][nt][q] = 0.f;

    #pragma unroll
    for (int kt = 0; kt < 8; kt++) {
        int kb = kt * 8 + tig;
        uint32_t ah[2][4], al[2][4];
        #pragma unroll
        for (int tt = 0; tt < 2; tt++) {
            int r0 = m0 + tt * 16 + g;
            ah[tt][0] = Ahi[r0       * PW + kb];
            ah[tt][1] = Ahi[(r0 + 8) * PW + kb];
            ah[tt][2] = Ahi[r0       * PW + kb + 4];
            ah[tt][3] = Ahi[(r0 + 8) * PW + kb + 4];
            al[tt][0] = Alo[r0       * PW + kb];
            al[tt][1] = Alo[(r0 + 8) * PW + kb];
            al[tt][2] = Alo[r0       * PW + kb + 4];
            al[tt][3] = Alo[(r0 + 8) * PW + kb + 4];
        }
        #pragma unroll
        for (int nt = 0; nt < 8; nt++) {
            int nc = nh * 64 + nt * 8 + g;
            uint32_t bh0 = Whi[nc * PW + kb], bh1 = Whi[nc * PW + kb + 4];
            uint32_t bl0 = Wlo[nc * PW + kb], bl1 = Wlo[nc * PW + kb + 4];
            #pragma unroll
            for (int tt = 0; tt < 2; tt++) {
                mma_bf16(C[tt][nt][0], C[tt][nt][1], C[tt][nt][2], C[tt][nt][3],
                         ah[tt][0], ah[tt][1], ah[tt][2], ah[tt][3], bh0, bh1);
                mma_bf16(C[tt][nt][0], C[tt][nt][1], C[tt][nt][2], C[tt][nt][3],
                         ah[tt][0], ah[tt][1], ah[tt][2], ah[tt][3], bl0, bl1);
                mma_bf16(C[tt][nt][0], C[tt][nt][1], C[tt][nt][2], C[tt][nt][3],
                         al[tt][0], al[tt][1], al[tt][2], al[tt][3], bh0, bh1);
            }
        }
    }

    #pragma unroll
    for (int tt = 0; tt < 2; tt++) {
        int r0 = n0g + m0 + tt * 16 + g;
        int r1 = r0 + 8;
        #pragma unroll
        for (int nt = 0; nt < 8; nt++) {
            int col = half * 128 + nh * 64 + nt * 8 + 2 * tig;
            if (r0 < N) *(float2*)(P + (size_t)r0 * PCOL + col) =
                make_float2(C[tt][nt][0], C[tt][nt][1]);
            if (r1 < N) *(float2*)(P + (size_t)r1 * PCOL + col) =
                make_float2(C[tt][nt][2], C[tt][nt][3]);
        }
    }
}

// ---------------------------------------------------------------------------
// Kernel 2: persistent fused edge pipeline, 32 edges per warp-chunk.
// ---------------------------------------------------------------------------
__global__ void __launch_bounds__(256, 1)
edge_kernel(const float* __restrict__ P,
            const int* __restrict__ eidx,        // [2][E] int32
            const float* __restrict__ attr,      // [E][2]
            const float* __restrict__ W1,        // rows 256,257
            const float* __restrict__ b1,
            const float* __restrict__ lng,
            const float* __restrict__ lnb,
            const float* __restrict__ W2,        // [128][64]
            const float* __restrict__ b2,
            const float* __restrict__ W3,
            const float* __restrict__ b3,
            float* __restrict__ out,
            int E)
{
    extern __shared__ uint32_t smu[];
    uint32_t* W2hi = smu;                      // [64][PW]
    uint32_t* W2lo = W2hi + 64 * PW;
    uint32_t* Xbase = W2lo + 64 * PW;          // 8 warps x (Xhi[32][PW], Xlo[32][PW])
    float* w3s = (float*)(Xbase + 8 * 2 * 32 * PW);   // 64
    float* b2s = w3s + 64;                             // 64
    float* b3s = b2s + 64;                             // 1

    int tid = threadIdx.x;

    for (int t = tid; t < 64 * 64; t += 256) {
        int kp = t >> 6, o = t & 63;
        float e0 = W2[(size_t)(2 * kp)     * 64 + o];
        float e1 = W2[(size_t)(2 * kp + 1) * 64 + o];
        uint32_t hi, lo; split_pair(e0, e1, hi, lo);
        W2hi[o * PW + kp] = hi; W2lo[o * PW + kp] = lo;
    }
    if (tid < 64) { w3s[tid] = W3[tid]; b2s[tid] = b2[tid]; }
    if (tid == 0) b3s[0] = b3[0];
    __syncthreads();

    int wid = tid >> 5, lane = tid & 31;
    int g = lane >> 2, tig = lane & 3;
    uint32_t* Xhi = Xbase + wid * 2 * 32 * PW;
    uint32_t* Xlo = Xhi + 32 * PW;
    int c0 = 4 * lane;
    const float inv_h = 1.0f / 128.0f;
    const float2* attr2 = (const float2*)attr;

    // ---- hoisted per-lane LN constants (loop-invariant) ----
    float4 w1a_r = *(const float4*)(W1 + 256 * HD + c0);
    float4 w1b_r = *(const float4*)(W1 + 257 * HD + c0);
    float4 b1_r  = *(const float4*)(b1 + c0);
    float4 g_r   = *(const float4*)(lng + c0);
    float4 be_r  = *(const float4*)(lnb + c0);
    float  b3v   = b3s[0];

    int nchunks = (E + 31) >> 5;
    int wg = blockIdx.x * 8 + wid;
    int wstride = gridDim.x * 8;

    for (int ch = wg; ch < nchunks; ch += wstride) {
        int e_base = ch << 5;

        // lane-parallel prefetch of 32 edges' indices/attrs
        int e_l = e_base + lane; if (e_l >= E) e_l = E - 1;
        int    i_l = eidx[e_l];
        int    j_l = eidx[(size_t)E + e_l];
        float2 a_l = attr2[e_l];

        // ---- gather + LN + ReLU + split-pack -> Xhi/Xlo (32 rows) ----
        #pragma unroll 4
        for (int ee = 0; ee < 32; ee++) {
            int   i  = __shfl_sync(0xffffffffu, i_l, ee);
            int   j  = __shfl_sync(0xffffffffu, j_l, ee);
            float ax = __shfl_sync(0xffffffffu, a_l.x, ee);
            float ay = __shfl_sync(0xffffffffu, a_l.y, ee);

            float4 pa = *(const float4*)(P + (size_t)i * PCOL + c0);
            float4 pb = *(const float4*)(P + (size_t)j * PCOL + 128 + c0);

            float h0 = pa.x + pb.x + ax * w1a_r.x + ay * w1b_r.x + b1_r.x;
            float h1 = pa.y + pb.y + ax * w1a_r.y + ay * w1b_r.y + b1_r.y;
            float h2 = pa.z + pb.z + ax * w1a_r.z + ay * w1b_r.z + b1_r.z;
            float h3 = pa.w + pb.w + ax * w1a_r.w + ay * w1b_r.w + b1_r.w;

            float s  = h0 + h1 + h2 + h3;
            float sq = h0 * h0 + h1 * h1 + h2 * h2 + h3 * h3;
            #pragma unroll
            for (int off = 16; off > 0; off >>= 1) {
                s  += __shfl_xor_sync(0xffffffffu, s,  off);
                sq += __shfl_xor_sync(0xffffffffu, sq, off);
            }
            float mean = s * inv_h;
            float var  = sq * inv_h - mean * mean;
            float rstd = rsqrtf(var + 1e-5f);

            float x0 = fmaxf((h0 - mean) * rstd * g_r.x + be_r.x, 0.f);
            float x1 = fmaxf((h1 - mean) * rstd * g_r.y + be_r.y, 0.f);
            float x2 = fmaxf((h2 - mean) * rstd * g_r.z + be_r.z, 0.f);
            float x3 = fmaxf((h3 - mean) * rstd * g_r.w + be_r.w, 0.f);

            uint32_t hA, lA, hB, lB;
            split_pair(x0, x1, hA, lA);
            split_pair(x2, x3, hB, lB);
            *(uint2*)(Xhi + ee * PW + 2 * lane) = make_uint2(hA, hB);
            *(uint2*)(Xlo + ee * PW + 2 * lane) = make_uint2(lA, lB);
        }
        __syncwarp();

        // ---- GEMM2: C[32][64] = X @ W2 + b2, two 16-row tiles share B ----
        float C[2][8][4];
        #pragma unroll
        for (int nt = 0; nt < 8; nt++) {
            float bb0 = b2s[8 * nt + 2 * tig];
            float bb1 = b2s[8 * nt + 2 * tig + 1];
            #pragma unroll
            for (int tt = 0; tt < 2; tt++) {
                C[tt][nt][0] = bb0; C[tt][nt][1] = bb1;
                C[tt][nt][2] = bb0; C[tt][nt][3] = bb1;
            }
        }

        #pragma unroll
        for (int kt = 0; kt < 8; kt++) {
            int kb = kt * 8 + tig;
            uint32_t ah[2][4], al[2][4];
            #pragma unroll
            for (int tt = 0; tt < 2; tt++) {
                int r0 = tt * 16 + g;
                ah[tt][0] = Xhi[r0       * PW + kb];
                ah[tt][1] = Xhi[(r0 + 8) * PW + kb];
                ah[tt][2] = Xhi[r0       * PW + kb + 4];
                ah[tt][3] = Xhi[(r0 + 8) * PW + kb + 4];
                al[tt][0] = Xlo[r0       * PW + kb];
                al[tt][1] = Xlo[(r0 + 8) * PW + kb];
                al[tt][2] = Xlo[r0       * PW + kb + 4];
                al[tt][3] = Xlo[(r0 + 8) * PW + kb + 4];
            }
            #pragma unroll
            for (int nt = 0; nt < 8; nt++) {
                int nc = 8 * nt + g;
                uint32_t bh0 = W2hi[nc * PW + kb], bh1 = W2hi[nc * PW + kb + 4];
                uint32_t bl0 = W2lo[nc * PW + kb], bl1 = W2lo[nc * PW + kb + 4];
                #pragma unroll
                for (int tt = 0; tt < 2; tt++) {
                    mma_bf16(C[tt][nt][0], C[tt][nt][1], C[tt][nt][2], C[tt][nt][3],
                             ah[tt][0], ah[tt][1], ah[tt][2], ah[tt][3], bh0, bh1);
                    mma_bf16(C[tt][nt][0], C[tt][nt][1], C[tt][nt][2], C[tt][nt][3],
                             ah[tt][0], ah[tt][1], ah[tt][2], ah[tt][3], bl0, bl1);
                    mma_bf16(C[tt][nt][0], C[tt][nt][1], C[tt][nt][2], C[tt][nt][3],
                             al[tt][0], al[tt][1], al[tt][2], al[tt][3], bh0, bh1);
                }
            }
        }
        __syncwarp();

        // ---- ReLU + W3 dot + reduce over tig ----
        #pragma unroll
        for (int tt = 0; tt < 2; tt++) {
            float p0 = 0.f, p1 = 0.f;
            #pragma unroll
            for (int nt = 0; nt < 8; nt++) {
                float w30 = w3s[8 * nt + 2 * tig];
                float w31 = w3s[8 * nt + 2 * tig + 1];
                p0 += fmaxf(C[tt][nt][0], 0.f) * w30 + fmaxf(C[tt][nt][1], 0.f) * w31;
                p1 += fmaxf(C[tt][nt][2], 0.f) * w30 + fmaxf(C[tt][nt][3], 0.f) * w31;
            }
            p0 += __shfl_xor_sync(0xffffffffu, p0, 1);
            p0 += __shfl_xor_sync(0xffffffffu, p0, 2);
            p1 += __shfl_xor_sync(0xffffffffu, p1, 1);
            p1 += __shfl_xor_sync(0xffffffffu, p1, 2);

            if (tig == 0) {
                int er0 = e_base + tt * 16 + g;
                int er1 = er0 + 8;
                if (er0 < E) out[er0] = p0 + b3v;
                if (er1 < E) out[er1] = p1 + b3v;
            }
        }
    }
}

// ---------------------------------------------------------------------------
// Launch
// ---------------------------------------------------------------------------
extern "C" void kernel_launch(void* const* d_in, const int* in_sizes, int n_in,
                              void* d_out, int out_size)
{
    const float* node_embed = (const float*)d_in[0];
    const int*   eidx       = (const int*)d_in[1];
    const float* attr       = (const float*)d_in[2];
    const float* W1         = (const float*)d_in[3];
    const float* b1         = (const float*)d_in[4];
    const float* lng        = (const float*)d_in[5];
    const float* lnb        = (const float*)d_in[6];
    const float* W2         = (const float*)d_in[7];
    const float* b2         = (const float*)d_in[8];
    const float* W3         = (const float*)d_in[9];
    const float* b3         = (const float*)d_in[10];
    float* out = (float*)d_out;

    int N = in_sizes[0] / HD;
    int E = in_sizes[2] / 2;

    float* P = nullptr;
    cudaGetSymbolAddress((void**)&P, g_P);

    const int PRE_SMEM  = 4 * 128 * PW * 4;                              // 139264 B
    const int EDGE_SMEM = (2 * 64 * PW + 8 * 2 * 32 * PW + 129) * 4;     // 174596 B

    cudaFuncSetAttribute(precompute_kernel,
                         cudaFuncAttributeMaxDynamicSharedMemorySize, PRE_SMEM);
    cudaFuncSetAttribute(edge_kernel,
                         cudaFuncAttributeMaxDynamicSharedMemorySize, EDGE_SMEM);

    dim3 pre_grid((N + 127) / 128, 2);
    precompute_kernel<<<pre_grid, 256, PRE_SMEM>>>(node_embed, W1, P, N);

    edge_kernel<<<148, 256, EDGE_SMEM>>>(P, eidx, attr, W1, b1, lng, lnb,
                                         W2, b2, W3, b3, out, E);
}

// round 6
// speedup vs baseline: 2.6272x; 1.2016x over previous
#include <cuda_runtime.h>
#include <cstdint>

// ---------------------------------------------------------------------------
// EdgeScoringMLP via bf16 tensor cores + 3-pass Dekker split (hi*hi+hi*lo+lo*hi).
//   logit(e) = W3 . relu( relu(LN(e_in @ W1 + b1)) @ W2 + b2 ) + b3
//   e_in @ W1 = Pa[i] + Pb[j] + a0*W1[256,:] + a1*W1[257,:]   (P precomputed)
// R6: edge kernel back to M=16/warp (2 CTAs/SM, 16 warps) while keeping
//     reg-hoisted LN constants and lane-parallel index prefetch from R5.
// ---------------------------------------------------------------------------

#define HD 128
#define PCOL 256
#define MAXN 100000
#define PW 68              // padded row stride (u32): (4g+tig)%32 all-distinct

__device__ float g_P[(size_t)MAXN * PCOL];

// ---- bf16 helpers ---------------------------------------------------------
static __device__ __forceinline__ uint32_t pack_bf16x2(float lo, float hi) {
    uint32_t d;
    asm("cvt.rn.bf16x2.f32 %0, %1, %2;" : "=r"(d) : "f"(hi), "f"(lo));
    return d;
}
static __device__ __forceinline__ void split_pair(float x0, float x1,
                                                  uint32_t& hi, uint32_t& lo) {
    hi = pack_bf16x2(x0, x1);
    float h0 = __uint_as_float(hi << 16);
    float h1 = __uint_as_float(hi & 0xFFFF0000u);
    lo = pack_bf16x2(x0 - h0, x1 - h1);
}
static __device__ __forceinline__ void mma_bf16(
    float& c0, float& c1, float& c2, float& c3,
    uint32_t a0, uint32_t a1, uint32_t a2, uint32_t a3,
    uint32_t b0, uint32_t b1)
{
    asm volatile(
        "mma.sync.aligned.m16n8k16.row.col.f32.bf16.bf16.f32 "
        "{%0,%1,%2,%3},{%4,%5,%6,%7},{%8,%9},{%0,%1,%2,%3};"
        : "+f"(c0), "+f"(c1), "+f"(c2), "+f"(c3)
        : "r"(a0), "r"(a1), "r"(a2), "r"(a3), "r"(b0), "r"(b1));
}

// ---------------------------------------------------------------------------
// Kernel 1: P = emb @ Wsel. CTA 256 thr = 8 warps, tile 128 nodes x 128 cols
// (blockIdx.y = half). Warp (mt 0..3, nh 0..1): 32 nodes x 64 cols, two
// 16-row mma tiles sharing B fragments.  (unchanged from R5)
// ---------------------------------------------------------------------------
__global__ void __launch_bounds__(256, 1)
precompute_kernel(const float* __restrict__ emb,
                  const float* __restrict__ W1,
                  float* __restrict__ P,
                  int N)
{
    extern __shared__ uint32_t smu[];
    uint32_t* Whi = smu;                  // [128][PW]  (o-major)
    uint32_t* Wlo = Whi + 128 * PW;
    uint32_t* Ahi = Wlo + 128 * PW;       // [128][PW]  (node-row major)
    uint32_t* Alo = Ahi + 128 * PW;

    int tid  = threadIdx.x;
    int half = blockIdx.y;
    int n0g  = blockIdx.x * 128;

    for (int t = tid; t < 128 * 64; t += 256) {
        int o = t & 127, kp = t >> 7;
        float e0 = W1[(size_t)(2 * kp     + half * 128) * HD + o];
        float e1 = W1[(size_t)(2 * kp + 1 + half * 128) * HD + o];
        uint32_t hi, lo; split_pair(e0, e1, hi, lo);
        Whi[o * PW + kp] = hi; Wlo[o * PW + kp] = lo;
    }
    for (int t = tid; t < 128 * 64; t += 256) {
        int r = t >> 6, kp = t & 63;
        int node = n0g + r; if (node >= N) node = N - 1;
        float2 v = *(const float2*)(emb + (size_t)node * HD + 2 * kp);
        uint32_t hi, lo; split_pair(v.x, v.y, hi, lo);
        Ahi[r * PW + kp] = hi; Alo[r * PW + kp] = lo;
    }
    __syncthreads();

    int wid = tid >> 5, lane = tid & 31;
    int g = lane >> 2, tig = lane & 3;
    int mt = wid >> 1, nh = wid & 1;
    int m0 = mt * 32;

    float C[2][8][4];
    #pragma unroll
    for (int tt = 0; tt < 2; tt++)
        #pragma unroll
        for (int nt = 0; nt < 8; nt++)
            #pragma unroll
            for (int q = 0; q < 4; q++) C[tt][nt][q] = 0.f;

    #pragma unroll
    for (int kt = 0; kt < 8; kt++) {
        int kb = kt * 8 + tig;
        uint32_t ah[2][4], al[2][4];
        #pragma unroll
        for (int tt = 0; tt < 2; tt++) {
            int r0 = m0 + tt * 16 + g;
            ah[tt][0] = Ahi[r0       * PW + kb];
            ah[tt][1] = Ahi[(r0 + 8) * PW + kb];
            ah[tt][2] = Ahi[r0       * PW + kb + 4];
            ah[tt][3] = Ahi[(r0 + 8) * PW + kb + 4];
            al[tt][0] = Alo[r0       * PW + kb];
            al[tt][1] = Alo[(r0 + 8) * PW + kb];
            al[tt][2] = Alo[r0       * PW + kb + 4];
            al[tt][3] = Alo[(r0 + 8) * PW + kb + 4];
        }
        #pragma unroll
        for (int nt = 0; nt < 8; nt++) {
            int nc = nh * 64 + nt * 8 + g;
            uint32_t bh0 = Whi[nc * PW + kb], bh1 = Whi[nc * PW + kb + 4];
            uint32_t bl0 = Wlo[nc * PW + kb], bl1 = Wlo[nc * PW + kb + 4];
            #pragma unroll
            for (int tt = 0; tt < 2; tt++) {
                mma_bf16(C[tt][nt][0], C[tt][nt][1], C[tt][nt][2], C[tt][nt][3],
                         ah[tt][0], ah[tt][1], ah[tt][2], ah[tt][3], bh0, bh1);
                mma_bf16(C[tt][nt][0], C[tt][nt][1], C[tt][nt][2], C[tt][nt][3],
                         ah[tt][0], ah[tt][1], ah[tt][2], ah[tt][3], bl0, bl1);
                mma_bf16(C[tt][nt][0], C[tt][nt][1], C[tt][nt][2], C[tt][nt][3],
                         al[tt][0], al[tt][1], al[tt][2], al[tt][3], bh0, bh1);
            }
        }
    }

    #pragma unroll
    for (int tt = 0; tt < 2; tt++) {
        int r0 = n0g + m0 + tt * 16 + g;
        int r1 = r0 + 8;
        #pragma unroll
        for (int nt = 0; nt < 8; nt++) {
            int col = half * 128 + nh * 64 + nt * 8 + 2 * tig;
            if (r0 < N) *(float2*)(P + (size_t)r0 * PCOL + col) =
                make_float2(C[tt][nt][0], C[tt][nt][1]);
            if (r1 < N) *(float2*)(P + (size_t)r1 * PCOL + col) =
                make_float2(C[tt][nt][2], C[tt][nt][3]);
        }
    }
}

// ---------------------------------------------------------------------------
// Kernel 2: persistent fused edge pipeline, 16 edges per warp-chunk,
// 2 CTAs/SM.  LN constants in registers; idx/attr prefetched lane-parallel.
// ---------------------------------------------------------------------------
__global__ void __launch_bounds__(256, 2)
edge_kernel(const float* __restrict__ P,
            const int* __restrict__ eidx,        // [2][E] int32
            const float* __restrict__ attr,      // [E][2]
            const float* __restrict__ W1,        // rows 256,257
            const float* __restrict__ b1,
            const float* __restrict__ lng,
            const float* __restrict__ lnb,
            const float* __restrict__ W2,        // [128][64]
            const float* __restrict__ b2,
            const float* __restrict__ W3,
            const float* __restrict__ b3,
            float* __restrict__ out,
            int E)
{
    extern __shared__ uint32_t smu[];
    uint32_t* W2hi = smu;                      // [64][PW]
    uint32_t* W2lo = W2hi + 64 * PW;
    uint32_t* Xbase = W2lo + 64 * PW;          // 8 warps x (Xhi[16][PW], Xlo[16][PW])
    float* w3s = (float*)(Xbase + 8 * 2 * 16 * PW);   // 64
    float* b2s = w3s + 64;                             // 64
    float* b3s = b2s + 64;                             // 1

    int tid = threadIdx.x;

    for (int t = tid; t < 64 * 64; t += 256) {
        int kp = t >> 6, o = t & 63;
        float e0 = W2[(size_t)(2 * kp)     * 64 + o];
        float e1 = W2[(size_t)(2 * kp + 1) * 64 + o];
        uint32_t hi, lo; split_pair(e0, e1, hi, lo);
        W2hi[o * PW + kp] = hi; W2lo[o * PW + kp] = lo;
    }
    if (tid < 64) { w3s[tid] = W3[tid]; b2s[tid] = b2[tid]; }
    if (tid == 0) b3s[0] = b3[0];
    __syncthreads();

    int wid = tid >> 5, lane = tid & 31;
    int g = lane >> 2, tig = lane & 3;
    uint32_t* Xhi = Xbase + wid * 2 * 16 * PW;
    uint32_t* Xlo = Xhi + 16 * PW;
    int c0 = 4 * lane;
    const float inv_h = 1.0f / 128.0f;
    const float2* attr2 = (const float2*)attr;

    // ---- hoisted per-lane LN constants (loop-invariant) ----
    float4 w1a_r = *(const float4*)(W1 + 256 * HD + c0);
    float4 w1b_r = *(const float4*)(W1 + 257 * HD + c0);
    float4 b1_r  = *(const float4*)(b1 + c0);
    float4 g_r   = *(const float4*)(lng + c0);
    float4 be_r  = *(const float4*)(lnb + c0);
    float  b3v   = b3s[0];

    int nchunks = (E + 15) >> 4;
    int wg = blockIdx.x * 8 + wid;
    int wstride = gridDim.x * 8;

    for (int ch = wg; ch < nchunks; ch += wstride) {
        int e_base = ch << 4;

        // lane-parallel prefetch of this chunk's 16 edges (lanes 0..15 used)
        int e_l = e_base + (lane & 15); if (e_l >= E) e_l = E - 1;
        int    i_l = eidx[e_l];
        int    j_l = eidx[(size_t)E + e_l];
        float2 a_l = attr2[e_l];

        // ---- gather + LN + ReLU + split-pack -> Xhi/Xlo (16 rows) ----
        #pragma unroll 4
        for (int ee = 0; ee < 16; ee++) {
            int   i  = __shfl_sync(0xffffffffu, i_l, ee);
            int   j  = __shfl_sync(0xffffffffu, j_l, ee);
            float ax = __shfl_sync(0xffffffffu, a_l.x, ee);
            float ay = __shfl_sync(0xffffffffu, a_l.y, ee);

            float4 pa = *(const float4*)(P + (size_t)i * PCOL + c0);
            float4 pb = *(const float4*)(P + (size_t)j * PCOL + 128 + c0);

            float h0 = pa.x + pb.x + ax * w1a_r.x + ay * w1b_r.x + b1_r.x;
            float h1 = pa.y + pb.y + ax * w1a_r.y + ay * w1b_r.y + b1_r.y;
            float h2 = pa.z + pb.z + ax * w1a_r.z + ay * w1b_r.z + b1_r.z;
            float h3 = pa.w + pb.w + ax * w1a_r.w + ay * w1b_r.w + b1_r.w;

            float s  = h0 + h1 + h2 + h3;
            float sq = h0 * h0 + h1 * h1 + h2 * h2 + h3 * h3;
            #pragma unroll
            for (int off = 16; off > 0; off >>= 1) {
                s  += __shfl_xor_sync(0xffffffffu, s,  off);
                sq += __shfl_xor_sync(0xffffffffu, sq, off);
            }
            float mean = s * inv_h;
            float var  = sq * inv_h - mean * mean;
            float rstd = rsqrtf(var + 1e-5f);

            float x0 = fmaxf((h0 - mean) * rstd * g_r.x + be_r.x, 0.f);
            float x1 = fmaxf((h1 - mean) * rstd * g_r.y + be_r.y, 0.f);
            float x2 = fmaxf((h2 - mean) * rstd * g_r.z + be_r.z, 0.f);
            float x3 = fmaxf((h3 - mean) * rstd * g_r.w + be_r.w, 0.f);

            uint32_t hA, lA, hB, lB;
            split_pair(x0, x1, hA, lA);
            split_pair(x2, x3, hB, lB);
            *(uint2*)(Xhi + ee * PW + 2 * lane) = make_uint2(hA, hB);
            *(uint2*)(Xlo + ee * PW + 2 * lane) = make_uint2(lA, lB);
        }
        __syncwarp();

        // ---- GEMM2: C[16][64] = X @ W2 + b2, 3-pass bf16 ----
        float C[8][4];
        #pragma unroll
        for (int nt = 0; nt < 8; nt++) {
            float bb0 = b2s[8 * nt + 2 * tig];
            float bb1 = b2s[8 * nt + 2 * tig + 1];
            C[nt][0] = bb0; C[nt][1] = bb1;
            C[nt][2] = bb0; C[nt][3] = bb1;
        }

        #pragma unroll
        for (int kt = 0; kt < 8; kt++) {
            int kb = kt * 8 + tig;
            uint32_t ah0 = Xhi[g       * PW + kb];
            uint32_t ah1 = Xhi[(g + 8) * PW + kb];
            uint32_t ah2 = Xhi[g       * PW + kb + 4];
            uint32_t ah3 = Xhi[(g + 8) * PW + kb + 4];
            uint32_t al0 = Xlo[g       * PW + kb];
            uint32_t al1 = Xlo[(g + 8) * PW + kb];
            uint32_t al2 = Xlo[g       * PW + kb + 4];
            uint32_t al3 = Xlo[(g + 8) * PW + kb + 4];
            #pragma unroll
            for (int nt = 0; nt < 8; nt++) {
                int nc = 8 * nt + g;
                uint32_t bh0 = W2hi[nc * PW + kb], bh1 = W2hi[nc * PW + kb + 4];
                uint32_t bl0 = W2lo[nc * PW + kb], bl1 = W2lo[nc * PW + kb + 4];
                mma_bf16(C[nt][0], C[nt][1], C[nt][2], C[nt][3],
                         ah0, ah1, ah2, ah3, bh0, bh1);
                mma_bf16(C[nt][0], C[nt][1], C[nt][2], C[nt][3],
                         ah0, ah1, ah2, ah3, bl0, bl1);
                mma_bf16(C[nt][0], C[nt][1], C[nt][2], C[nt][3],
                         al0, al1, al2, al3, bh0, bh1);
            }
        }
        __syncwarp();

        // ---- ReLU + W3 dot + reduce over tig ----
        float p0 = 0.f, p1 = 0.f;
        #pragma unroll
        for (int nt = 0; nt < 8; nt++) {
            float w30 = w3s[8 * nt + 2 * tig];
            float w31 = w3s[8 * nt + 2 * tig + 1];
            p0 += fmaxf(C[nt][0], 0.f) * w30 + fmaxf(C[nt][1], 0.f) * w31;
            p1 += fmaxf(C[nt][2], 0.f) * w30 + fmaxf(C[nt][3], 0.f) * w31;
        }
        p0 += __shfl_xor_sync(0xffffffffu, p0, 1);
        p0 += __shfl_xor_sync(0xffffffffu, p0, 2);
        p1 += __shfl_xor_sync(0xffffffffu, p1, 1);
        p1 += __shfl_xor_sync(0xffffffffu, p1, 2);

        if (tig == 0) {
            int er0 = e_base + g;
            int er1 = er0 + 8;
            if (er0 < E) out[er0] = p0 + b3v;
            if (er1 < E) out[er1] = p1 + b3v;
        }
    }
}

// ---------------------------------------------------------------------------
// Launch
// ---------------------------------------------------------------------------
extern "C" void kernel_launch(void* const* d_in, const int* in_sizes, int n_in,
                              void* d_out, int out_size)
{
    const float* node_embed = (const float*)d_in[0];
    const int*   eidx       = (const int*)d_in[1];
    const float* attr       = (const float*)d_in[2];
    const float* W1         = (const float*)d_in[3];
    const float* b1         = (const float*)d_in[4];
    const float* lng        = (const float*)d_in[5];
    const float* lnb        = (const float*)d_in[6];
    const float* W2         = (const float*)d_in[7];
    const float* b2         = (const float*)d_in[8];
    const float* W3         = (const float*)d_in[9];
    const float* b3         = (const float*)d_in[10];
    float* out = (float*)d_out;

    int N = in_sizes[0] / HD;
    int E = in_sizes[2] / 2;

    float* P = nullptr;
    cudaGetSymbolAddress((void**)&P, g_P);

    const int PRE_SMEM  = 4 * 128 * PW * 4;                              // 139264 B
    const int EDGE_SMEM = (2 * 64 * PW + 8 * 2 * 16 * PW + 129) * 4;     // 104964 B

    cudaFuncSetAttribute(precompute_kernel,
                         cudaFuncAttributeMaxDynamicSharedMemorySize, PRE_SMEM);
    cudaFuncSetAttribute(edge_kernel,
                         cudaFuncAttributeMaxDynamicSharedMemorySize, EDGE_SMEM);

    dim3 pre_grid((N + 127) / 128, 2);
    precompute_kernel<<<pre_grid, 256, PRE_SMEM>>>(node_embed, W1, P, N);

    edge_kernel<<<296, 256, EDGE_SMEM>>>(P, eidx, attr, W1, b1, lng, lnb,
                                         W2, b2, W3, b3, out, E);
}